// round 2
// baseline (speedup 1.0000x reference)
#include <cuda_runtime.h>

#define B_  4
#define L_  2048
#define D_  1024
#define H_  16
#define HD_ 64
#define M_  (B_*L_)   // 8192

// Scratch (allocation-free rule: __device__ globals)
__device__ float g_q[(size_t)B_*H_*L_*HD_];   // [B,H,L,hd]
__device__ float g_k[(size_t)B_*H_*L_*HD_];
__device__ float g_v[(size_t)B_*H_*L_*HD_];
__device__ float g_att[(size_t)M_*D_];        // [B,L,D] attention output pre-projection

// C[m,n] = sum_k X[m,k]*W[n,k]  (i.e. x @ W.T), 64x64 block tiles, 4x4 per thread.
// MODE==1: X = x input, grid.z selects (Wq,Wk,Wv) -> (g_q,g_k,g_v) in [B,H,L,hd] layout.
// MODE==0: X = g_att, W = W0 (=Wo), Out = d_out with bias.
template<int MODE>
__global__ __launch_bounds__(256) void gemm64(
    const float* __restrict__ X,
    const float* __restrict__ W0,
    const float* __restrict__ W1,
    const float* __restrict__ W2,
    const float* __restrict__ bias,
    float* __restrict__ Out)
{
    __shared__ float As[32*64];   // [k][m] transposed
    __shared__ float Bs[32*64];   // [k][n] transposed
    const int tid = threadIdx.x;
    const int tx = tid & 15, ty = tid >> 4;
    const int m0 = blockIdx.y * 64;
    const int n0 = blockIdx.x * 64;

    const float* W = W0;
    float* gout = nullptr;
    if (MODE == 1) {
        int z = blockIdx.z;
        W    = (z == 0) ? W0  : (z == 1 ? W1  : W2);
        gout = (z == 0) ? g_q : (z == 1 ? g_k : g_v);
    }
    const float* Xp = (MODE == 0) ? g_att : X;

    const int lm = tid & 63;        // row within tile for loading
    const int lk = (tid >> 6) * 8;  // k base (8 floats = 2 float4)

    float acc[4][4] = {};
    for (int k0 = 0; k0 < D_; k0 += 32) {
        float4 xa = *(const float4*)(Xp + (size_t)(m0 + lm) * D_ + k0 + lk);
        float4 xb = *(const float4*)(Xp + (size_t)(m0 + lm) * D_ + k0 + lk + 4);
        float4 wa = *(const float4*)(W  + (size_t)(n0 + lm) * D_ + k0 + lk);
        float4 wb = *(const float4*)(W  + (size_t)(n0 + lm) * D_ + k0 + lk + 4);
        __syncthreads();
        {
            float tb[8];
            *(float4*)(tb) = xa; *(float4*)(tb + 4) = xb;
            #pragma unroll
            for (int u = 0; u < 8; u++) As[(lk + u) * 64 + lm] = tb[u];
            *(float4*)(tb) = wa; *(float4*)(tb + 4) = wb;
            #pragma unroll
            for (int u = 0; u < 8; u++) Bs[(lk + u) * 64 + lm] = tb[u];
        }
        __syncthreads();
        #pragma unroll
        for (int k = 0; k < 32; k++) {
            float4 a = *(const float4*)&As[k * 64 + 4 * ty];
            float4 b = *(const float4*)&Bs[k * 64 + 4 * tx];
            float av[4] = {a.x, a.y, a.z, a.w};
            float bv[4] = {b.x, b.y, b.z, b.w};
            #pragma unroll
            for (int i = 0; i < 4; i++)
                #pragma unroll
                for (int j = 0; j < 4; j++)
                    acc[i][j] = fmaf(av[i], bv[j], acc[i][j]);
        }
    }

    if (MODE == 0) {
        #pragma unroll
        for (int i = 0; i < 4; i++) {
            int m = m0 + 4 * ty + i;
            #pragma unroll
            for (int j = 0; j < 4; j++) {
                int n = n0 + 4 * tx + j;
                Out[(size_t)m * D_ + n] = acc[i][j] + bias[n];
            }
        }
    } else {
        #pragma unroll
        for (int i = 0; i < 4; i++) {
            int m = m0 + 4 * ty + i;
            int b = m >> 11, l = m & (L_ - 1);
            #pragma unroll
            for (int j = 0; j < 4; j++) {
                int n = n0 + 4 * tx + j;
                int h = n >> 6, d = n & 63;
                gout[(((size_t)(b * H_ + h)) * L_ + l) * HD_ + d] = acc[i][j];
            }
        }
    }
}

// Fused attention per (b, h, 64-query tile):
// Phase 1: stream K tiles, compute scaled scores, write RAW scores into A region
//          (L2-resident scratch), maintain online softmax stats (m, l).
// Phase 2: read scores back (L2-hot), write normalized A in place, accumulate A*V.
__global__ __launch_bounds__(256) void attn_kernel(float* __restrict__ A)
{
    __shared__ float sA[64 * 68];   // phase1: q^T [d][r]; phase2: P [r][c]
    __shared__ float sB[64 * 68];   // phase1: k^T [d][c]; phase2: V [c][d]
    __shared__ float ms[64], ls[64];

    const int tid = threadIdx.x;
    const int tx = tid & 15, ty = tid >> 4;
    const int q0 = blockIdx.x * 64;
    const int h  = blockIdx.y;
    const int b  = blockIdx.z;
    const size_t bh = (size_t)(b * H_ + h);
    const float* qh = g_q + bh * L_ * HD_;
    const float* kh = g_k + bh * L_ * HD_;
    const float* vh = g_v + bh * L_ * HD_;
    const size_t abase = (bh * L_ + q0) * (size_t)L_;

    const int lc = tid & 63;
    const int ld = (tid >> 6) * 16;

    // Load Q tile transposed: sA[d][r]
    {
        const float* qp = qh + (size_t)(q0 + lc) * HD_ + ld;
        float4 t0 = *(const float4*)(qp);
        float4 t1 = *(const float4*)(qp + 4);
        float4 t2 = *(const float4*)(qp + 8);
        float4 t3 = *(const float4*)(qp + 12);
        float tb[16];
        *(float4*)(tb) = t0; *(float4*)(tb + 4) = t1;
        *(float4*)(tb + 8) = t2; *(float4*)(tb + 12) = t3;
        #pragma unroll
        for (int u = 0; u < 16; u++) sA[(ld + u) * 68 + lc] = tb[u];
    }
    if (tid < 64) { ms[tid] = -1e30f; ls[tid] = 0.f; }

    // ---------------- Phase 1: scores + online softmax stats ----------------
    for (int kt = 0; kt < 32; kt++) {
        const float* kp = kh + (size_t)(kt * 64 + lc) * HD_ + ld;
        float4 t0 = *(const float4*)(kp);
        float4 t1 = *(const float4*)(kp + 4);
        float4 t2 = *(const float4*)(kp + 8);
        float4 t3 = *(const float4*)(kp + 12);
        __syncthreads();
        {
            float tb[16];
            *(float4*)(tb) = t0; *(float4*)(tb + 4) = t1;
            *(float4*)(tb + 8) = t2; *(float4*)(tb + 12) = t3;
            #pragma unroll
            for (int u = 0; u < 16; u++) sB[(ld + u) * 68 + lc] = tb[u];
        }
        __syncthreads();

        float s[4][4] = {};
        #pragma unroll
        for (int d = 0; d < 64; d++) {
            float4 a  = *(const float4*)&sA[d * 68 + 4 * ty];
            float4 bb = *(const float4*)&sB[d * 68 + 4 * tx];
            float av[4] = {a.x, a.y, a.z, a.w};
            float bv[4] = {bb.x, bb.y, bb.z, bb.w};
            #pragma unroll
            for (int i = 0; i < 4; i++)
                #pragma unroll
                for (int j = 0; j < 4; j++)
                    s[i][j] = fmaf(av[i], bv[j], s[i][j]);
        }

        float tm[4], te[4];
        #pragma unroll
        for (int i = 0; i < 4; i++) {
            #pragma unroll
            for (int j = 0; j < 4; j++) s[i][j] *= 0.125f;   // 1/sqrt(64)
            // write raw scaled scores to the A region (scratch; normalized later)
            float* ap = A + abase + (size_t)(4 * ty + i) * L_ + kt * 64 + 4 * tx;
            *(float4*)ap = make_float4(s[i][0], s[i][1], s[i][2], s[i][3]);
            // row max over this 64-wide tile (16 threads share a row = half-warp)
            float mx = fmaxf(fmaxf(s[i][0], s[i][1]), fmaxf(s[i][2], s[i][3]));
            #pragma unroll
            for (int o = 8; o >= 1; o >>= 1)
                mx = fmaxf(mx, __shfl_xor_sync(0xffffffffu, mx, o));
            tm[i] = mx;
            float e = __expf(s[i][0] - mx) + __expf(s[i][1] - mx)
                    + __expf(s[i][2] - mx) + __expf(s[i][3] - mx);
            #pragma unroll
            for (int o = 8; o >= 1; o >>= 1)
                e += __shfl_xor_sync(0xffffffffu, e, o);
            te[i] = e;
        }
        if (tx == 0) {
            #pragma unroll
            for (int i = 0; i < 4; i++) {
                int r = 4 * ty + i;
                float mo = ms[r];
                float mn = fmaxf(mo, tm[i]);
                ls[r] = ls[r] * __expf(mo - mn) + te[i] * __expf(tm[i] - mn);
                ms[r] = mn;
            }
        }
    }

    __syncthreads();
    if (tid < 64) ls[tid] = 1.0f / ls[tid];
    __syncthreads();

    // Cache this thread's 4 row stats in registers for phase 2
    float rm[4], rl[4];
    #pragma unroll
    for (int i = 0; i < 4; i++) { rm[i] = ms[4 * ty + i]; rl[i] = ls[4 * ty + i]; }

    // ---------------- Phase 2: normalize A in place + accumulate A*V ----------------
    float vacc[4][4] = {};
    for (int kt = 0; kt < 32; kt++) {
        const float* vp = vh + (size_t)(kt * 64 + lc) * HD_ + ld;
        float4 v0 = __ldg((const float4*)(vp));
        float4 v1 = __ldg((const float4*)(vp + 4));
        float4 v2 = __ldg((const float4*)(vp + 8));
        float4 v3 = __ldg((const float4*)(vp + 12));
        float4 srow[4];
        #pragma unroll
        for (int i = 0; i < 4; i++)
            srow[i] = *(const float4*)(A + abase + (size_t)(4 * ty + i) * L_ + kt * 64 + 4 * tx);
        __syncthreads();
        *(float4*)&sB[lc * 68 + ld]      = v0;
        *(float4*)&sB[lc * 68 + ld + 4]  = v1;
        *(float4*)&sB[lc * 68 + ld + 8]  = v2;
        *(float4*)&sB[lc * 68 + ld + 12] = v3;
        #pragma unroll
        for (int i = 0; i < 4; i++) {
            int r = 4 * ty + i;
            float m = rm[i], li = rl[i];
            float4 p;
            p.x = __expf(srow[i].x - m) * li;
            p.y = __expf(srow[i].y - m) * li;
            p.z = __expf(srow[i].z - m) * li;
            p.w = __expf(srow[i].w - m) * li;
            *(float4*)(A + abase + (size_t)r * L_ + kt * 64 + 4 * tx) = p;   // final A
            *(float4*)&sA[r * 68 + 4 * tx] = p;
        }
        __syncthreads();
        #pragma unroll
        for (int c = 0; c < 64; c++) {
            float4 bb = *(const float4*)&sB[c * 68 + 4 * tx];
            float bv[4] = {bb.x, bb.y, bb.z, bb.w};
            #pragma unroll
            for (int i = 0; i < 4; i++) {
                float a = sA[(4 * ty + i) * 68 + c];
                #pragma unroll
                for (int j = 0; j < 4; j++)
                    vacc[i][j] = fmaf(a, bv[j], vacc[i][j]);
            }
        }
    }
    #pragma unroll
    for (int i = 0; i < 4; i++) {
        float* op = g_att + ((size_t)(b * L_ + q0 + 4 * ty + i)) * D_ + h * HD_ + 4 * tx;
        *(float4*)op = make_float4(vacc[i][0], vacc[i][1], vacc[i][2], vacc[i][3]);
    }
}

extern "C" void kernel_launch(void* const* d_in, const int* in_sizes, int n_in,
                              void* d_out, int out_size) {
    const float* x  = (const float*)d_in[0];
    // d_in[1] = key_indices: unused by the reference computation
    const float* Wq = (const float*)d_in[2];
    const float* Wk = (const float*)d_in[3];
    const float* Wv = (const float*)d_in[4];
    const float* Wo = (const float*)d_in[5];
    const float* bo = (const float*)d_in[6];
    float* out = (float*)d_out;
    float* A   = out + (size_t)M_ * D_;   // A follows out in the flattened output

    // 1) q,k,v projections (one launch, z selects the weight)
    gemm64<1><<<dim3(16, 128, 3), 256>>>(x, Wq, Wk, Wv, nullptr, nullptr);
    // 2) fused scores -> softmax (A materialized) -> A*V
    attn_kernel<<<dim3(32, 16, 4), 256>>>(A);
    // 3) output projection with bias
    gemm64<0><<<dim3(16, 128, 1), 256>>>(nullptr, Wo, nullptr, nullptr, bo, out);
}

// round 4
// speedup vs baseline: 1.5037x; 1.5037x over previous
#include <cuda_runtime.h>
#include <cuda_bf16.h>
#include <cstdint>

#define B_  4
#define L_  2048
#define D_  1024
#define H_  16
#define HD_ 64
#define M_  (B_*L_)   // 8192

// ---------------- scratch (__device__ globals; no allocs allowed) ----------------
__device__ float g_q[(size_t)B_*H_*L_*HD_];   // [B,H,L,hd]
__device__ float g_k[(size_t)B_*H_*L_*HD_];
__device__ float g_v[(size_t)B_*H_*L_*HD_];
__device__ float g_att[(size_t)M_*D_];        // [B,L,D] attention output pre-projection

__device__ __nv_bfloat16 g_xhi[(size_t)M_*D_], g_xlo[(size_t)M_*D_];
__device__ __nv_bfloat16 g_whi[(size_t)4*D_*D_], g_wlo[(size_t)4*D_*D_];
__device__ __nv_bfloat16 g_ahi[(size_t)M_*D_], g_alo[(size_t)M_*D_];

// ---------------- helpers ----------------
__device__ __forceinline__ uint32_t smem_u32(const void* p) {
    uint32_t a;
    asm("{ .reg .u64 t; cvta.to.shared.u64 t, %1; cvt.u32.u64 %0, t; }" : "=r"(a) : "l"(p));
    return a;
}
__device__ __forceinline__ void cpasync16(uint32_t dst, const void* src) {
    asm volatile("cp.async.cg.shared.global [%0], [%1], 16;" :: "r"(dst), "l"(src));
}
__device__ __forceinline__ void mma16816(float* d, const uint32_t* a, const uint32_t* b) {
    asm volatile(
        "mma.sync.aligned.m16n8k16.row.col.f32.bf16.bf16.f32 "
        "{%0,%1,%2,%3}, {%4,%5,%6,%7}, {%8,%9}, {%0,%1,%2,%3};"
        : "+f"(d[0]), "+f"(d[1]), "+f"(d[2]), "+f"(d[3])
        : "r"(a[0]), "r"(a[1]), "r"(a[2]), "r"(a[3]), "r"(b[0]), "r"(b[1]));
}

// ---------------- fp32 -> bf16 hi/lo split ----------------
__global__ __launch_bounds__(256) void split_kernel(const float* __restrict__ src, int sel, int z, int n4)
{
    int i = blockIdx.x * blockDim.x + threadIdx.x;
    if (i >= n4) return;
    __nv_bfloat16 *hi, *lo;
    const float* s = src;
    if (sel == 0)      { hi = g_xhi; lo = g_xlo; }
    else if (sel == 1) { hi = g_whi + (size_t)z * D_ * D_; lo = g_wlo + (size_t)z * D_ * D_; }
    else               { hi = g_ahi; lo = g_alo; s = g_att; }
    float4 v = ((const float4*)s)[i];
    __nv_bfloat16 h0 = __float2bfloat16(v.x), h1 = __float2bfloat16(v.y);
    __nv_bfloat16 h2 = __float2bfloat16(v.z), h3 = __float2bfloat16(v.w);
    __nv_bfloat16 l0 = __float2bfloat16(v.x - __bfloat162float(h0));
    __nv_bfloat16 l1 = __float2bfloat16(v.y - __bfloat162float(h1));
    __nv_bfloat16 l2 = __float2bfloat16(v.z - __bfloat162float(h2));
    __nv_bfloat16 l3 = __float2bfloat16(v.w - __bfloat162float(h3));
    __nv_bfloat162* hp = (__nv_bfloat162*)(hi + 4 * (size_t)i);
    __nv_bfloat162* lp = (__nv_bfloat162*)(lo + 4 * (size_t)i);
    hp[0] = __halves2bfloat162(h0, h1); hp[1] = __halves2bfloat162(h2, h3);
    lp[0] = __halves2bfloat162(l0, l1); lp[1] = __halves2bfloat162(l2, l3);
}

// ---------------- HMMA (mma.sync) GEMM: C[m,n] = sum_k X[m,k]*W[n,k] ----------------
// CTA 128x128, 8 warps (warp tile 32x64), K-chunk 64, double-buffered cp.async smem.
// smem per matrix: 128 rows x 36 words (64 bf16 + 8 pad) -> conflict-free frag loads.
#define SRW  36                 // row stride in 32-bit words
#define MATW (128*SRW)          // words per matrix tile
#define BUFW (4*MATW)           // words per buffer (Ah,Al,Bh,Bl)
#define GSM_BYTES (2*BUFW*4)    // 147456 bytes

template<int MODE>
__global__ __launch_bounds__(256) void gemm_mma(const float* __restrict__ bias, float* __restrict__ Out)
{
    extern __shared__ char smch[];
    uint32_t* s32 = (uint32_t*)smch;
    const uint32_t sb = smem_u32(smch);

    const int tid = threadIdx.x, lane = tid & 31, wid = tid >> 5;
    const int wm = wid & 3, wn = wid >> 2;
    const int g = lane >> 2, cc = lane & 3;
    const int n0 = blockIdx.x * 128, m0 = blockIdx.y * 128;

    const __nv_bfloat16 *Ahp, *Alp, *Whp, *Wlp;
    float* out;
    if (MODE == 1) {
        int z = blockIdx.z;
        Ahp = g_xhi; Alp = g_xlo;
        Whp = g_whi + (size_t)z * D_ * D_; Wlp = g_wlo + (size_t)z * D_ * D_;
        out = (z == 0) ? g_q : (z == 1) ? g_k : g_v;
    } else {
        Ahp = g_ahi; Alp = g_alo;
        Whp = g_whi + (size_t)3 * D_ * D_; Wlp = g_wlo + (size_t)3 * D_ * D_;
        out = Out;
    }

    // loader mapping: row r = tid>>1 (0..127), half = tid&1 covers 32 bf16
    const int r = tid >> 1, half = tid & 1;
    const size_t garow = (size_t)(m0 + r) * D_ + half * 32;
    const size_t gbrow = (size_t)(n0 + r) * D_ + half * 32;
    const uint32_t sdst = sb + (uint32_t)(r * SRW + half * 16) * 4;

    auto issue_chunk = [&](int c) {
        const int k0 = c * 64;
        const uint32_t d0 = sdst + (uint32_t)((c & 1) * BUFW) * 4;
        const __nv_bfloat16* pa = Ahp + garow + k0;
        const __nv_bfloat16* pl = Alp + garow + k0;
        const __nv_bfloat16* pb = Whp + gbrow + k0;
        const __nv_bfloat16* pq = Wlp + gbrow + k0;
        #pragma unroll
        for (int j = 0; j < 4; j++) {
            cpasync16(d0 + j * 16,                 pa + j * 8);
            cpasync16(d0 + MATW * 4 + j * 16,      pl + j * 8);
            cpasync16(d0 + 2 * MATW * 4 + j * 16,  pb + j * 8);
            cpasync16(d0 + 3 * MATW * 4 + j * 16,  pq + j * 8);
        }
    };

    float d[2][8][4] = {};

    issue_chunk(0);
    asm volatile("cp.async.commit_group;" ::: "memory");

    for (int c = 0; c < 16; c++) {
        if (c < 15) {
            issue_chunk(c + 1);
            asm volatile("cp.async.commit_group;" ::: "memory");
            asm volatile("cp.async.wait_group 1;" ::: "memory");
        } else {
            asm volatile("cp.async.wait_group 0;" ::: "memory");
        }
        __syncthreads();

        const uint32_t* bufp = s32 + (c & 1) * BUFW;
        const uint32_t* pAh = bufp;
        const uint32_t* pAl = bufp + MATW;
        const uint32_t* pBh = bufp + 2 * MATW;
        const uint32_t* pBl = bufp + 3 * MATW;

        #pragma unroll
        for (int ks = 0; ks < 4; ks++) {
            const int kw = ks * 8;
            uint32_t ah[2][4], al[2][4];
            #pragma unroll
            for (int mi = 0; mi < 2; mi++) {
                const int ra = (wm * 32 + mi * 16 + g) * SRW + kw + cc;
                ah[mi][0] = pAh[ra];              ah[mi][1] = pAh[ra + 8 * SRW];
                ah[mi][2] = pAh[ra + 4];          ah[mi][3] = pAh[ra + 8 * SRW + 4];
                al[mi][0] = pAl[ra];              al[mi][1] = pAl[ra + 8 * SRW];
                al[mi][2] = pAl[ra + 4];          al[mi][3] = pAl[ra + 8 * SRW + 4];
            }
            #pragma unroll
            for (int nq = 0; nq < 2; nq++) {
                uint32_t bh[4][2], bl[4][2];
                #pragma unroll
                for (int nn = 0; nn < 4; nn++) {
                    const int rb = (wn * 64 + nq * 32 + nn * 8 + g) * SRW + kw + cc;
                    bh[nn][0] = pBh[rb]; bh[nn][1] = pBh[rb + 4];
                    bl[nn][0] = pBl[rb]; bl[nn][1] = pBl[rb + 4];
                }
                #pragma unroll
                for (int nn = 0; nn < 4; nn++)
                    #pragma unroll
                    for (int mi = 0; mi < 2; mi++) {
                        float* dd = d[mi][nq * 4 + nn];
                        mma16816(dd, ah[mi], bh[nn]);
                        mma16816(dd, ah[mi], bl[nn]);
                        mma16816(dd, al[mi], bh[nn]);
                    }
            }
        }
        __syncthreads();
    }

    // epilogue
    #pragma unroll
    for (int mi = 0; mi < 2; mi++) {
        const int row = m0 + wm * 32 + mi * 16 + g;
        #pragma unroll
        for (int ni = 0; ni < 8; ni++) {
            const int col = n0 + wn * 64 + ni * 8 + cc * 2;
            float* dd = d[mi][ni];
            if (MODE == 1) {
                int b = row >> 11, l = row & (L_ - 1);
                int h = col >> 6, dp = col & 63;
                float* o0 = out + ((size_t)(b * H_ + h) * L_ + l) * HD_ + dp;
                float* o1 = out + ((size_t)(b * H_ + h) * L_ + (l + 8)) * HD_ + dp;  // row+8 same b (8192 rows, 2048/b, row%2048<2040 guaranteed since g<8, +8 stays in 16-block)
                *(float2*)o0 = make_float2(dd[0], dd[1]);
                *(float2*)o1 = make_float2(dd[2], dd[3]);
            } else {
                float bx = bias[col], by = bias[col + 1];
                *(float2*)(out + (size_t)row * D_ + col) =
                    make_float2(dd[0] + bx, dd[1] + by);
                *(float2*)(out + (size_t)(row + 8) * D_ + col) =
                    make_float2(dd[2] + bx, dd[3] + by);
            }
        }
    }
}

// ---------------- fused attention (unchanged; SIMT fp32, verified) ----------------
__global__ __launch_bounds__(256) void attn_kernel(float* __restrict__ A)
{
    __shared__ float sA[64 * 68];
    __shared__ float sB[64 * 68];
    __shared__ float ms[64], ls[64];

    const int tid = threadIdx.x;
    const int tx = tid & 15, ty = tid >> 4;
    const int q0 = blockIdx.x * 64;
    const int h  = blockIdx.y;
    const int b  = blockIdx.z;
    const size_t bh = (size_t)(b * H_ + h);
    const float* qh = g_q + bh * L_ * HD_;
    const float* kh = g_k + bh * L_ * HD_;
    const float* vh = g_v + bh * L_ * HD_;
    const size_t abase = (bh * L_ + q0) * (size_t)L_;

    const int lc = tid & 63;
    const int ld = (tid >> 6) * 16;

    {
        const float* qp = qh + (size_t)(q0 + lc) * HD_ + ld;
        float4 t0 = *(const float4*)(qp);
        float4 t1 = *(const float4*)(qp + 4);
        float4 t2 = *(const float4*)(qp + 8);
        float4 t3 = *(const float4*)(qp + 12);
        float tb[16];
        *(float4*)(tb) = t0; *(float4*)(tb + 4) = t1;
        *(float4*)(tb + 8) = t2; *(float4*)(tb + 12) = t3;
        #pragma unroll
        for (int u = 0; u < 16; u++) sA[(ld + u) * 68 + lc] = tb[u];
    }
    if (tid < 64) { ms[tid] = -1e30f; ls[tid] = 0.f; }

    for (int kt = 0; kt < 32; kt++) {
        const float* kp = kh + (size_t)(kt * 64 + lc) * HD_ + ld;
        float4 t0 = *(const float4*)(kp);
        float4 t1 = *(const float4*)(kp + 4);
        float4 t2 = *(const float4*)(kp + 8);
        float4 t3 = *(const float4*)(kp + 12);
        __syncthreads();
        {
            float tb[16];
            *(float4*)(tb) = t0; *(float4*)(tb + 4) = t1;
            *(float4*)(tb + 8) = t2; *(float4*)(tb + 12) = t3;
            #pragma unroll
            for (int u = 0; u < 16; u++) sB[(ld + u) * 68 + lc] = tb[u];
        }
        __syncthreads();

        float s[4][4] = {};
        #pragma unroll
        for (int dd = 0; dd < 64; dd++) {
            float4 a  = *(const float4*)&sA[dd * 68 + 4 * ty];
            float4 bb = *(const float4*)&sB[dd * 68 + 4 * tx];
            float av[4] = {a.x, a.y, a.z, a.w};
            float bv[4] = {bb.x, bb.y, bb.z, bb.w};
            #pragma unroll
            for (int i = 0; i < 4; i++)
                #pragma unroll
                for (int j = 0; j < 4; j++)
                    s[i][j] = fmaf(av[i], bv[j], s[i][j]);
        }

        float tm[4], te[4];
        #pragma unroll
        for (int i = 0; i < 4; i++) {
            #pragma unroll
            for (int j = 0; j < 4; j++) s[i][j] *= 0.125f;
            float* ap = A + abase + (size_t)(4 * ty + i) * L_ + kt * 64 + 4 * tx;
            *(float4*)ap = make_float4(s[i][0], s[i][1], s[i][2], s[i][3]);
            float mx = fmaxf(fmaxf(s[i][0], s[i][1]), fmaxf(s[i][2], s[i][3]));
            #pragma unroll
            for (int o = 8; o >= 1; o >>= 1)
                mx = fmaxf(mx, __shfl_xor_sync(0xffffffffu, mx, o));
            tm[i] = mx;
            float e = __expf(s[i][0] - mx) + __expf(s[i][1] - mx)
                    + __expf(s[i][2] - mx) + __expf(s[i][3] - mx);
            #pragma unroll
            for (int o = 8; o >= 1; o >>= 1)
                e += __shfl_xor_sync(0xffffffffu, e, o);
            te[i] = e;
        }
        if (tx == 0) {
            #pragma unroll
            for (int i = 0; i < 4; i++) {
                int rr = 4 * ty + i;
                float mo = ms[rr];
                float mn = fmaxf(mo, tm[i]);
                ls[rr] = ls[rr] * __expf(mo - mn) + te[i] * __expf(tm[i] - mn);
                ms[rr] = mn;
            }
        }
    }

    __syncthreads();
    if (tid < 64) ls[tid] = 1.0f / ls[tid];
    __syncthreads();

    float rm[4], rl[4];
    #pragma unroll
    for (int i = 0; i < 4; i++) { rm[i] = ms[4 * ty + i]; rl[i] = ls[4 * ty + i]; }

    float vacc[4][4] = {};
    for (int kt = 0; kt < 32; kt++) {
        const float* vp = vh + (size_t)(kt * 64 + lc) * HD_ + ld;
        float4 v0 = __ldg((const float4*)(vp));
        float4 v1 = __ldg((const float4*)(vp + 4));
        float4 v2 = __ldg((const float4*)(vp + 8));
        float4 v3 = __ldg((const float4*)(vp + 12));
        float4 srow[4];
        #pragma unroll
        for (int i = 0; i < 4; i++)
            srow[i] = *(const float4*)(A + abase + (size_t)(4 * ty + i) * L_ + kt * 64 + 4 * tx);
        __syncthreads();
        *(float4*)&sB[lc * 68 + ld]      = v0;
        *(float4*)&sB[lc * 68 + ld + 4]  = v1;
        *(float4*)&sB[lc * 68 + ld + 8]  = v2;
        *(float4*)&sB[lc * 68 + ld + 12] = v3;
        #pragma unroll
        for (int i = 0; i < 4; i++) {
            int rr = 4 * ty + i;
            float m = rm[i], li = rl[i];
            float4 p;
            p.x = __expf(srow[i].x - m) * li;
            p.y = __expf(srow[i].y - m) * li;
            p.z = __expf(srow[i].z - m) * li;
            p.w = __expf(srow[i].w - m) * li;
            *(float4*)(A + abase + (size_t)rr * L_ + kt * 64 + 4 * tx) = p;
            *(float4*)&sA[rr * 68 + 4 * tx] = p;
        }
        __syncthreads();
        #pragma unroll
        for (int ccx = 0; ccx < 64; ccx++) {
            float4 bb = *(const float4*)&sB[ccx * 68 + 4 * tx];
            float bv[4] = {bb.x, bb.y, bb.z, bb.w};
            #pragma unroll
            for (int i = 0; i < 4; i++) {
                float a = sA[(4 * ty + i) * 68 + ccx];
                #pragma unroll
                for (int j = 0; j < 4; j++)
                    vacc[i][j] = fmaf(a, bv[j], vacc[i][j]);
            }
        }
    }
    #pragma unroll
    for (int i = 0; i < 4; i++) {
        float* op = g_att + ((size_t)(b * L_ + q0 + 4 * ty + i)) * D_ + h * HD_ + 4 * tx;
        *(float4*)op = make_float4(vacc[i][0], vacc[i][1], vacc[i][2], vacc[i][3]);
    }
}

extern "C" void kernel_launch(void* const* d_in, const int* in_sizes, int n_in,
                              void* d_out, int out_size) {
    const float* x  = (const float*)d_in[0];
    // d_in[1] = key_indices: unused by the reference computation
    const float* bo = (const float*)d_in[6];
    float* out = (float*)d_out;
    float* A   = out + (size_t)M_ * D_;

    cudaFuncSetAttribute(gemm_mma<1>, cudaFuncAttributeMaxDynamicSharedMemorySize, GSM_BYTES);
    cudaFuncSetAttribute(gemm_mma<0>, cudaFuncAttributeMaxDynamicSharedMemorySize, GSM_BYTES);

    // bf16 hi/lo splits of x and the 4 weights
    split_kernel<<<(M_*D_/4 + 255)/256, 256>>>(x, 0, 0, M_*D_/4);
    for (int z = 0; z < 4; z++)
        split_kernel<<<(D_*D_/4 + 255)/256, 256>>>((const float*)d_in[2 + z], 1, z, D_*D_/4);

    // q,k,v projections on tensor cores (z selects weight/output)
    gemm_mma<1><<<dim3(8, 64, 3), 256, GSM_BYTES>>>(nullptr, nullptr);

    // fused scores -> softmax (A materialized) -> A*V  (fp32 SIMT)
    attn_kernel<<<dim3(32, 16, 4), 256>>>(A);

    // split att output, then output projection + bias on tensor cores
    split_kernel<<<(M_*D_/4 + 255)/256, 256>>>(nullptr, 2, 0, M_*D_/4);
    gemm_mma<0><<<dim3(8, 64, 1), 256, GSM_BYTES>>>(bo, out);
}

// round 5
// speedup vs baseline: 2.1476x; 1.4282x over previous
#include <cuda_runtime.h>
#include <cuda_bf16.h>
#include <cstdint>

#define B_  4
#define L_  2048
#define D_  1024
#define H_  16
#define HD_ 64
#define M_  (B_*L_)   // 8192

// ---------------- scratch (__device__ globals; no allocs allowed) ----------------
__device__ __nv_bfloat16 g_xhi[(size_t)M_*D_], g_xlo[(size_t)M_*D_];
__device__ __nv_bfloat16 g_whi[(size_t)4*D_*D_], g_wlo[(size_t)4*D_*D_];
__device__ __nv_bfloat16 g_qhi[(size_t)B_*H_*L_*HD_], g_qlo[(size_t)B_*H_*L_*HD_];
__device__ __nv_bfloat16 g_khi[(size_t)B_*H_*L_*HD_], g_klo[(size_t)B_*H_*L_*HD_];
__device__ __nv_bfloat16 g_vhi[(size_t)B_*H_*L_*HD_], g_vlo[(size_t)B_*H_*L_*HD_];
__device__ __nv_bfloat16 g_ahi[(size_t)M_*D_], g_alo[(size_t)M_*D_];

// ---------------- helpers ----------------
__device__ __forceinline__ uint32_t smem_u32(const void* p) {
    uint32_t a;
    asm("{ .reg .u64 t; cvta.to.shared.u64 t, %1; cvt.u32.u64 %0, t; }" : "=r"(a) : "l"(p));
    return a;
}
__device__ __forceinline__ void cpasync16(uint32_t dst, const void* src) {
    asm volatile("cp.async.cg.shared.global [%0], [%1], 16;" :: "r"(dst), "l"(src));
}
__device__ __forceinline__ void mma16816(float* d, const uint32_t* a, const uint32_t* b) {
    asm volatile(
        "mma.sync.aligned.m16n8k16.row.col.f32.bf16.bf16.f32 "
        "{%0,%1,%2,%3}, {%4,%5,%6,%7}, {%8,%9}, {%0,%1,%2,%3};"
        : "+f"(d[0]), "+f"(d[1]), "+f"(d[2]), "+f"(d[3])
        : "r"(a[0]), "r"(a[1]), "r"(a[2]), "r"(a[3]), "r"(b[0]), "r"(b[1]));
}
__device__ __forceinline__ uint32_t packhl(float a, float b) {
    __nv_bfloat162 t = __halves2bfloat162(__float2bfloat16(a), __float2bfloat16(b));
    return *(uint32_t*)&t;
}
__device__ __forceinline__ uint32_t packres(float a, float b, uint32_t hw) {
    __nv_bfloat162 hv = *(__nv_bfloat162*)&hw;
    return packhl(a - __bfloat162float(hv.x), b - __bfloat162float(hv.y));
}

// ---------------- fp32 -> bf16 hi/lo split (x and weights) ----------------
__global__ __launch_bounds__(256) void split_kernel(const float* __restrict__ src, int sel, int z, int n4)
{
    int i = blockIdx.x * blockDim.x + threadIdx.x;
    if (i >= n4) return;
    __nv_bfloat16 *hi, *lo;
    if (sel == 0) { hi = g_xhi; lo = g_xlo; }
    else          { hi = g_whi + (size_t)z * D_ * D_; lo = g_wlo + (size_t)z * D_ * D_; }
    float4 v = ((const float4*)src)[i];
    uint32_t h0 = packhl(v.x, v.y), h1 = packhl(v.z, v.w);
    uint32_t l0 = packres(v.x, v.y, h0), l1 = packres(v.z, v.w, h1);
    ((uint32_t*)(hi + 4 * (size_t)i))[0] = h0; ((uint32_t*)(hi + 4 * (size_t)i))[1] = h1;
    ((uint32_t*)(lo + 4 * (size_t)i))[0] = l0; ((uint32_t*)(lo + 4 * (size_t)i))[1] = l1;
}

// ---------------- HMMA GEMM: C[m,n] = sum_k X[m,k]*W[n,k] ----------------
#define SRW  36
#define MATW (128*SRW)
#define BUFW (4*MATW)
#define GSM_BYTES (2*BUFW*4)

template<int MODE>
__global__ __launch_bounds__(256) void gemm_mma(const float* __restrict__ bias, float* __restrict__ Out)
{
    extern __shared__ char smch[];
    uint32_t* s32 = (uint32_t*)smch;
    const uint32_t sb = smem_u32(smch);

    const int tid = threadIdx.x, lane = tid & 31, wid = tid >> 5;
    const int wm = wid & 3, wn = wid >> 2;
    const int g = lane >> 2, cc = lane & 3;
    const int n0 = blockIdx.x * 128, m0 = blockIdx.y * 128;

    const __nv_bfloat16 *Ahp, *Alp, *Whp, *Wlp;
    int z = 0;
    if (MODE == 1) {
        z = blockIdx.z;
        Ahp = g_xhi; Alp = g_xlo;
        Whp = g_whi + (size_t)z * D_ * D_; Wlp = g_wlo + (size_t)z * D_ * D_;
    } else {
        Ahp = g_ahi; Alp = g_alo;
        Whp = g_whi + (size_t)3 * D_ * D_; Wlp = g_wlo + (size_t)3 * D_ * D_;
    }

    const int r = tid >> 1, half = tid & 1;
    const size_t garow = (size_t)(m0 + r) * D_ + half * 32;
    const size_t gbrow = (size_t)(n0 + r) * D_ + half * 32;
    const uint32_t sdst = sb + (uint32_t)(r * SRW + half * 16) * 4;

    auto issue_chunk = [&](int c) {
        const int k0 = c * 64;
        const uint32_t d0 = sdst + (uint32_t)((c & 1) * BUFW) * 4;
        const __nv_bfloat16* pa = Ahp + garow + k0;
        const __nv_bfloat16* pl = Alp + garow + k0;
        const __nv_bfloat16* pb = Whp + gbrow + k0;
        const __nv_bfloat16* pq = Wlp + gbrow + k0;
        #pragma unroll
        for (int j = 0; j < 4; j++) {
            cpasync16(d0 + j * 16,                 pa + j * 8);
            cpasync16(d0 + MATW * 4 + j * 16,      pl + j * 8);
            cpasync16(d0 + 2 * MATW * 4 + j * 16,  pb + j * 8);
            cpasync16(d0 + 3 * MATW * 4 + j * 16,  pq + j * 8);
        }
    };

    float d[2][8][4] = {};

    issue_chunk(0);
    asm volatile("cp.async.commit_group;" ::: "memory");

    for (int c = 0; c < 16; c++) {
        if (c < 15) {
            issue_chunk(c + 1);
            asm volatile("cp.async.commit_group;" ::: "memory");
            asm volatile("cp.async.wait_group 1;" ::: "memory");
        } else {
            asm volatile("cp.async.wait_group 0;" ::: "memory");
        }
        __syncthreads();

        const uint32_t* bufp = s32 + (c & 1) * BUFW;
        const uint32_t* pAh = bufp;
        const uint32_t* pAl = bufp + MATW;
        const uint32_t* pBh = bufp + 2 * MATW;
        const uint32_t* pBl = bufp + 3 * MATW;

        #pragma unroll
        for (int ks = 0; ks < 4; ks++) {
            const int kw = ks * 8;
            uint32_t ah[2][4], al[2][4];
            #pragma unroll
            for (int mi = 0; mi < 2; mi++) {
                const int ra = (wm * 32 + mi * 16 + g) * SRW + kw + cc;
                ah[mi][0] = pAh[ra];     ah[mi][1] = pAh[ra + 8 * SRW];
                ah[mi][2] = pAh[ra + 4]; ah[mi][3] = pAh[ra + 8 * SRW + 4];
                al[mi][0] = pAl[ra];     al[mi][1] = pAl[ra + 8 * SRW];
                al[mi][2] = pAl[ra + 4]; al[mi][3] = pAl[ra + 8 * SRW + 4];
            }
            #pragma unroll
            for (int nq = 0; nq < 2; nq++) {
                uint32_t bh[4][2], bl[4][2];
                #pragma unroll
                for (int nn = 0; nn < 4; nn++) {
                    const int rb = (wn * 64 + nq * 32 + nn * 8 + g) * SRW + kw + cc;
                    bh[nn][0] = pBh[rb]; bh[nn][1] = pBh[rb + 4];
                    bl[nn][0] = pBl[rb]; bl[nn][1] = pBl[rb + 4];
                }
                #pragma unroll
                for (int nn = 0; nn < 4; nn++)
                    #pragma unroll
                    for (int mi = 0; mi < 2; mi++) {
                        float* dd = d[mi][nq * 4 + nn];
                        mma16816(dd, ah[mi], bh[nn]);
                        mma16816(dd, ah[mi], bl[nn]);
                        mma16816(dd, al[mi], bh[nn]);
                    }
            }
        }
        __syncthreads();
    }

    // epilogue
    #pragma unroll
    for (int mi = 0; mi < 2; mi++) {
        const int row = m0 + wm * 32 + mi * 16 + g;
        #pragma unroll
        for (int ni = 0; ni < 8; ni++) {
            const int col = n0 + wn * 64 + ni * 8 + cc * 2;
            float* dd = d[mi][ni];
            if (MODE == 1) {
                __nv_bfloat16* ohi = (z == 0) ? g_qhi : (z == 1) ? g_khi : g_vhi;
                __nv_bfloat16* olo = (z == 0) ? g_qlo : (z == 1) ? g_klo : g_vlo;
                int b = row >> 11, l = row & (L_ - 1);
                int hh = col >> 6, dp = col & 63;
                size_t base = ((size_t)(b * H_ + hh) * L_ + l) * HD_ + dp;
                uint32_t h0 = packhl(dd[0], dd[1]), h1 = packhl(dd[2], dd[3]);
                *(uint32_t*)(ohi + base)           = h0;
                *(uint32_t*)(ohi + base + 8 * HD_) = h1;
                *(uint32_t*)(olo + base)           = packres(dd[0], dd[1], h0);
                *(uint32_t*)(olo + base + 8 * HD_) = packres(dd[2], dd[3], h1);
            } else {
                float bx = bias[col], by = bias[col + 1];
                *(float2*)(Out + (size_t)row * D_ + col) =
                    make_float2(dd[0] + bx, dd[1] + by);
                *(float2*)(Out + (size_t)(row + 8) * D_ + col) =
                    make_float2(dd[2] + bx, dd[3] + by);
            }
        }
    }
}

// ---------------- tensor-core attention ----------------
// Per CTA: (b, h, 64 query rows). Phase 1: S = Q*K^T (3-term hi/lo MMA), raw scaled
// scores -> A scratch (same-thread readback), online (m,l). Phase 2: p=exp(s-m)/l,
// final A in place, P hi/lo + V^T staged in smem, O += P*V^T (3-term MMA).
#define SQ   36
#define SP   68
#define WQ_LO 2304          // 64*SQ
#define WK0   4608          // after Q hi+lo
#define WVT_HI 4608
#define WVT_LO 8960         // +64*SP
#define WP_HI  13312
#define WP_LO  17664
#define ASM_BYTES (23040*4) // 92160

__global__ __launch_bounds__(256) void attn_mma(float* __restrict__ A)
{
    extern __shared__ uint32_t s32[];
    __shared__ float ms[64], ls[64], pm[64][4], pl[64][4];

    const int tid = threadIdx.x, lane = tid & 31, wid = tid >> 5;
    const int g = lane >> 2, cc = lane & 3;
    const int wm = wid & 1,  wn = wid >> 1;    // phase 1: 2 m-warps x 4 n-warps
    const int wm2 = wid & 3, wn2 = wid >> 2;   // phase 2: 4 m-warps x 2 n-warps
    const int q0 = blockIdx.x * 64, h = blockIdx.y, b = blockIdx.z;
    const int bh = b * H_ + h;
    const __nv_bfloat16* qhi = g_qhi + (size_t)bh * L_ * HD_;
    const __nv_bfloat16* qlo = g_qlo + (size_t)bh * L_ * HD_;
    const __nv_bfloat16* khi = g_khi + (size_t)bh * L_ * HD_;
    const __nv_bfloat16* klo = g_klo + (size_t)bh * L_ * HD_;
    const __nv_bfloat16* vhi = g_vhi + (size_t)bh * L_ * HD_;
    const __nv_bfloat16* vlo = g_vlo + (size_t)bh * L_ * HD_;
    float* Ab = A + ((size_t)bh * L_ + q0) * L_;
    const uint32_t sb = smem_u32(s32);

    // Q tile 64x64 hi/lo -> smem
    {
        const int r = tid >> 2, qw = tid & 3;
        const __nv_bfloat16* sh = qhi + (size_t)(q0 + r) * HD_ + qw * 16;
        const __nv_bfloat16* sl = qlo + (size_t)(q0 + r) * HD_ + qw * 16;
        *(uint4*)&s32[r * SQ + qw * 8]             = *(const uint4*)sh;
        *(uint4*)&s32[r * SQ + qw * 8 + 4]         = *(const uint4*)(sh + 8);
        *(uint4*)&s32[WQ_LO + r * SQ + qw * 8]     = *(const uint4*)sl;
        *(uint4*)&s32[WQ_LO + r * SQ + qw * 8 + 4] = *(const uint4*)(sl + 8);
    }
    if (tid < 64) { ms[tid] = -1e30f; ls[tid] = 0.f; }

    auto loadK = [&](int kt) {
        const int r = tid >> 1, half = tid & 1;
        const uint32_t bo = WK0 + (kt & 1) * 9216;
        const __nv_bfloat16* sh = khi + (size_t)(kt * 128 + r) * HD_ + half * 32;
        const __nv_bfloat16* sl = klo + (size_t)(kt * 128 + r) * HD_ + half * 32;
        const uint32_t dh = sb + (bo + r * SQ + half * 16) * 4;
        const uint32_t dl = sb + (bo + 128 * SQ + r * SQ + half * 16) * 4;
        #pragma unroll
        for (int j = 0; j < 4; j++) {
            cpasync16(dh + j * 16, sh + j * 8);
            cpasync16(dl + j * 16, sl + j * 8);
        }
    };

    loadK(0);
    asm volatile("cp.async.commit_group;" ::: "memory");

    // ---------------- phase 1 ----------------
    for (int kt = 0; kt < 16; kt++) {
        if (kt < 15) {
            loadK(kt + 1);
            asm volatile("cp.async.commit_group;" ::: "memory");
            asm volatile("cp.async.wait_group 1;" ::: "memory");
        } else {
            asm volatile("cp.async.wait_group 0;" ::: "memory");
        }
        __syncthreads();

        const uint32_t* Kh = s32 + WK0 + (kt & 1) * 9216;
        const uint32_t* Kl = Kh + 128 * SQ;

        float d[2][4][4] = {};
        #pragma unroll
        for (int ks = 0; ks < 4; ks++) {
            const int kw = ks * 8;
            uint32_t ah[2][4], al[2][4];
            #pragma unroll
            for (int mi = 0; mi < 2; mi++) {
                const int ra = (wm * 32 + mi * 16 + g) * SQ + kw + cc;
                ah[mi][0] = s32[ra];     ah[mi][1] = s32[ra + 8 * SQ];
                ah[mi][2] = s32[ra + 4]; ah[mi][3] = s32[ra + 8 * SQ + 4];
                al[mi][0] = s32[WQ_LO + ra];     al[mi][1] = s32[WQ_LO + ra + 8 * SQ];
                al[mi][2] = s32[WQ_LO + ra + 4]; al[mi][3] = s32[WQ_LO + ra + 8 * SQ + 4];
            }
            #pragma unroll
            for (int nn = 0; nn < 4; nn++) {
                const int rb = (wn * 32 + nn * 8 + g) * SQ + kw + cc;
                uint32_t bhf[2] = {Kh[rb], Kh[rb + 4]};
                uint32_t blf[2] = {Kl[rb], Kl[rb + 4]};
                #pragma unroll
                for (int mi = 0; mi < 2; mi++) {
                    mma16816(d[mi][nn], ah[mi], bhf);
                    mma16816(d[mi][nn], ah[mi], blf);
                    mma16816(d[mi][nn], al[mi], bhf);
                }
            }
        }
        // scale, write raw scores, per-row stats
        #pragma unroll
        for (int mi = 0; mi < 2; mi++)
        #pragma unroll
        for (int ch = 0; ch < 2; ch++) {
            const int row = wm * 32 + mi * 16 + g + 8 * ch;
            float v[8];
            #pragma unroll
            for (int nn = 0; nn < 4; nn++) {
                v[2*nn]   = d[mi][nn][2*ch]   * 0.125f;
                v[2*nn+1] = d[mi][nn][2*ch+1] * 0.125f;
                *(float2*)(Ab + (size_t)row * L_ + kt * 128 + wn * 32 + nn * 8 + cc * 2)
                    = make_float2(v[2*nn], v[2*nn+1]);
            }
            float mx = v[0];
            #pragma unroll
            for (int j = 1; j < 8; j++) mx = fmaxf(mx, v[j]);
            mx = fmaxf(mx, __shfl_xor_sync(0xffffffffu, mx, 1));
            mx = fmaxf(mx, __shfl_xor_sync(0xffffffffu, mx, 2));
            float e = 0.f;
            #pragma unroll
            for (int j = 0; j < 8; j++) e += __expf(v[j] - mx);
            e += __shfl_xor_sync(0xffffffffu, e, 1);
            e += __shfl_xor_sync(0xffffffffu, e, 2);
            if (cc == 0) { pm[row][wn] = mx; pl[row][wn] = e; }
        }
        __syncthreads();
        if (tid < 64) {
            float mo = ms[tid], lo = ls[tid];
            #pragma unroll
            for (int w = 0; w < 4; w++) {
                float mw = pm[tid][w], lw = pl[tid][w];
                float mn = fmaxf(mo, mw);
                lo = lo * __expf(mo - mn) + lw * __expf(mw - mn);
                mo = mn;
            }
            ms[tid] = mo; ls[tid] = lo;
        }
    }
    __syncthreads();
    if (tid < 64) ls[tid] = 1.0f / ls[tid];

    // ---------------- phase 2 ----------------
    float o[4][4] = {};
    for (int kt = 0; kt < 16; kt++) {
        __syncthreads();   // smem overlay / prior-chunk reuse guard (also publishes inv-ls)
        // V chunk -> VT smem (hi/lo)
        {
            const int sp = tid >> 2, dblk = tid & 3;
            const __nv_bfloat16* s0h = vhi + (size_t)(kt * 128 + 2 * sp) * HD_ + dblk * 16;
            const __nv_bfloat16* s0l = vlo + (size_t)(kt * 128 + 2 * sp) * HD_ + dblk * 16;
            unsigned short r0h[16], r1h[16], r0l[16], r1l[16];
            *(uint4*)r0h       = *(const uint4*)s0h;
            *(uint4*)(r0h + 8) = *(const uint4*)(s0h + 8);
            *(uint4*)r1h       = *(const uint4*)(s0h + HD_);
            *(uint4*)(r1h + 8) = *(const uint4*)(s0h + HD_ + 8);
            *(uint4*)r0l       = *(const uint4*)s0l;
            *(uint4*)(r0l + 8) = *(const uint4*)(s0l + 8);
            *(uint4*)r1l       = *(const uint4*)(s0l + HD_);
            *(uint4*)(r1l + 8) = *(const uint4*)(s0l + HD_ + 8);
            #pragma unroll
            for (int j = 0; j < 16; j++) {
                const int dd = dblk * 16 + j;
                s32[WVT_HI + dd * SP + sp] = (uint32_t)r0h[j] | ((uint32_t)r1h[j] << 16);
                s32[WVT_LO + dd * SP + sp] = (uint32_t)r0l[j] | ((uint32_t)r1l[j] << 16);
            }
        }
        // P build: readback own raw scores, finalize A, stage P hi/lo
        #pragma unroll
        for (int mi = 0; mi < 2; mi++)
        #pragma unroll
        for (int ch = 0; ch < 2; ch++) {
            const int row = wm * 32 + mi * 16 + g + 8 * ch;
            const float m = ms[row], il = ls[row];
            #pragma unroll
            for (int nn = 0; nn < 4; nn++) {
                float* ap = Ab + (size_t)row * L_ + kt * 128 + wn * 32 + nn * 8 + cc * 2;
                float2 s = *(float2*)ap;
                float p0 = __expf(s.x - m) * il;
                float p1 = __expf(s.y - m) * il;
                *(float2*)ap = make_float2(p0, p1);
                uint32_t hw = packhl(p0, p1);
                uint32_t lw = packres(p0, p1, hw);
                s32[WP_HI + row * SP + wn * 16 + nn * 4 + cc] = hw;
                s32[WP_LO + row * SP + wn * 16 + nn * 4 + cc] = lw;
            }
        }
        __syncthreads();
        // O += P * VT
        #pragma unroll
        for (int ks = 0; ks < 8; ks++) {
            const int kw = ks * 8;
            const int ra = (wm2 * 16 + g) * SP + kw + cc;
            uint32_t ah2[4] = {s32[WP_HI + ra], s32[WP_HI + ra + 8 * SP],
                               s32[WP_HI + ra + 4], s32[WP_HI + ra + 8 * SP + 4]};
            uint32_t al2[4] = {s32[WP_LO + ra], s32[WP_LO + ra + 8 * SP],
                               s32[WP_LO + ra + 4], s32[WP_LO + ra + 8 * SP + 4]};
            #pragma unroll
            for (int nn = 0; nn < 4; nn++) {
                const int rb = (wn2 * 32 + nn * 8 + g) * SP + kw + cc;
                uint32_t bhf[2] = {s32[WVT_HI + rb], s32[WVT_HI + rb + 4]};
                uint32_t blf[2] = {s32[WVT_LO + rb], s32[WVT_LO + rb + 4]};
                mma16816(o[nn], ah2, bhf);
                mma16816(o[nn], al2, bhf);
                mma16816(o[nn], ah2, blf);
            }
        }
    }

    // epilogue: O -> g_ahi/g_alo at [b*L + q0+row][h*64 + col]
    #pragma unroll
    for (int nn = 0; nn < 4; nn++)
    #pragma unroll
    for (int ch = 0; ch < 2; ch++) {
        const int row = wm2 * 16 + g + 8 * ch;
        const int col = wn2 * 32 + nn * 8 + cc * 2;
        const size_t base = ((size_t)(b * L_ + q0 + row)) * D_ + h * HD_ + col;
        float v0 = o[nn][2 * ch], v1 = o[nn][2 * ch + 1];
        uint32_t hw = packhl(v0, v1);
        *(uint32_t*)(g_ahi + base) = hw;
        *(uint32_t*)(g_alo + base) = packres(v0, v1, hw);
    }
}

extern "C" void kernel_launch(void* const* d_in, const int* in_sizes, int n_in,
                              void* d_out, int out_size) {
    const float* x  = (const float*)d_in[0];
    // d_in[1] = key_indices: unused by the reference computation
    const float* bo = (const float*)d_in[6];
    float* out = (float*)d_out;
    float* A   = out + (size_t)M_ * D_;

    cudaFuncSetAttribute(gemm_mma<1>, cudaFuncAttributeMaxDynamicSharedMemorySize, GSM_BYTES);
    cudaFuncSetAttribute(gemm_mma<0>, cudaFuncAttributeMaxDynamicSharedMemorySize, GSM_BYTES);
    cudaFuncSetAttribute(attn_mma,    cudaFuncAttributeMaxDynamicSharedMemorySize, ASM_BYTES);

    // bf16 hi/lo splits of x and the 4 weights
    split_kernel<<<(M_*D_/4 + 255)/256, 256>>>(x, 0, 0, M_*D_/4);
    for (int z = 0; z < 4; z++)
        split_kernel<<<(D_*D_/4 + 255)/256, 256>>>((const float*)d_in[2 + z], 1, z, D_*D_/4);

    // q,k,v projections on tensor cores -> bf16 hi/lo q/k/v
    gemm_mma<1><<<dim3(8, 64, 3), 256, GSM_BYTES>>>(nullptr, nullptr);

    // tensor-core attention: A materialized + attn output as hi/lo
    attn_mma<<<dim3(32, 16, 4), 256, ASM_BYTES>>>(A);

    // output projection + bias on tensor cores
    gemm_mma<0><<<dim3(8, 64, 1), 256, GSM_BYTES>>>(bo, out);
}

// round 8
// speedup vs baseline: 2.2437x; 1.0447x over previous
#include <cuda_runtime.h>
#include <cuda_bf16.h>
#include <cstdint>

#define B_  4
#define L_  2048
#define D_  1024
#define H_  16
#define HD_ 64
#define M_  (B_*L_)   // 8192

// ---------------- scratch (__device__ globals; no allocs allowed) ----------------
__device__ __nv_bfloat16 g_xhi[(size_t)M_*D_], g_xlo[(size_t)M_*D_];
__device__ __nv_bfloat16 g_whi[(size_t)4*D_*D_], g_wlo[(size_t)4*D_*D_];
__device__ __nv_bfloat16 g_qhi[(size_t)B_*H_*L_*HD_], g_qlo[(size_t)B_*H_*L_*HD_];
__device__ __nv_bfloat16 g_khi[(size_t)B_*H_*L_*HD_], g_klo[(size_t)B_*H_*L_*HD_];
__device__ __nv_bfloat16 g_vhi[(size_t)B_*H_*L_*HD_], g_vlo[(size_t)B_*H_*L_*HD_];
__device__ __nv_bfloat16 g_ahi[(size_t)M_*D_], g_alo[(size_t)M_*D_];

// ---------------- helpers ----------------
__device__ __forceinline__ uint32_t smem_u32(const void* p) {
    uint32_t a;
    asm("{ .reg .u64 t; cvta.to.shared.u64 t, %1; cvt.u32.u64 %0, t; }" : "=r"(a) : "l"(p));
    return a;
}
__device__ __forceinline__ void cpasync16(uint32_t dst, const void* src) {
    asm volatile("cp.async.cg.shared.global [%0], [%1], 16;" :: "r"(dst), "l"(src));
}
__device__ __forceinline__ void mma16816(float* d, const uint32_t* a, const uint32_t* b) {
    asm volatile(
        "mma.sync.aligned.m16n8k16.row.col.f32.bf16.bf16.f32 "
        "{%0,%1,%2,%3}, {%4,%5,%6,%7}, {%8,%9}, {%0,%1,%2,%3};"
        : "+f"(d[0]), "+f"(d[1]), "+f"(d[2]), "+f"(d[3])
        : "r"(a[0]), "r"(a[1]), "r"(a[2]), "r"(a[3]), "r"(b[0]), "r"(b[1]));
}
__device__ __forceinline__ void ldm4(uint32_t* r, uint32_t a) {
    asm volatile("ldmatrix.sync.aligned.m8n8.x4.shared.b16 {%0,%1,%2,%3}, [%4];"
        : "=r"(r[0]), "=r"(r[1]), "=r"(r[2]), "=r"(r[3]) : "r"(a));
}
__device__ __forceinline__ void ldm4t(uint32_t* r, uint32_t a) {
    asm volatile("ldmatrix.sync.aligned.m8n8.x4.trans.shared.b16 {%0,%1,%2,%3}, [%4];"
        : "=r"(r[0]), "=r"(r[1]), "=r"(r[2]), "=r"(r[3]) : "r"(a));
}
// A-type x4 (16 rows x k16): r0=rows0-7/k0-7, r1=rows8-15/k0-7, r2=rows0-7/k8-15, r3=rows8-15/k8-15
__device__ __forceinline__ uint32_t ldmA_addr(uint32_t base, int S, int row0, int lane) {
    int lr = lane & 7, sel = lane >> 3;
    return base + (uint32_t)((row0 + lr + (sel & 1) * 8) * S + (sel & 2) * 2) * 4;
}
// B-type x4 non-trans (two n-blocks n0, n0+8; k16): r0=b[n0][k0-7], r1=b[n0][k8-15], r2=b[n0+8][..], r3=..
__device__ __forceinline__ uint32_t ldmB_addr(uint32_t base, int S, int n0, int lane) {
    int lr = lane & 7, sel = lane >> 3;
    return base + (uint32_t)((n0 + lr + (sel >> 1) * 8) * S + (sel & 1) * 4) * 4;
}
// B-type x4 trans (row-major V: k rows x n cols; two n-blocks n0, n0+8)
__device__ __forceinline__ uint32_t ldmBT_addr(uint32_t base, int S, int n0, int lane) {
    int lr = lane & 7, sel = lane >> 3;
    return base + (uint32_t)((lr + (sel & 1) * 8) * S + (n0 + (sel >> 1) * 8) / 2) * 4;
}
__device__ __forceinline__ uint32_t packhl(float a, float b) {
    __nv_bfloat162 t = __halves2bfloat162(__float2bfloat16(a), __float2bfloat16(b));
    return *(uint32_t*)&t;
}
__device__ __forceinline__ uint32_t packres(float a, float b, uint32_t hw) {
    __nv_bfloat162 hv = *(__nv_bfloat162*)&hw;
    return packhl(a - __bfloat162float(hv.x), b - __bfloat162float(hv.y));
}

// ---------------- fp32 -> bf16 hi/lo split (x and weights) ----------------
__global__ __launch_bounds__(256) void split_kernel(const float* __restrict__ src, int sel, int z, int n4)
{
    int i = blockIdx.x * blockDim.x + threadIdx.x;
    if (i >= n4) return;
    __nv_bfloat16 *hi, *lo;
    if (sel == 0) { hi = g_xhi; lo = g_xlo; }
    else          { hi = g_whi + (size_t)z * D_ * D_; lo = g_wlo + (size_t)z * D_ * D_; }
    float4 v = ((const float4*)src)[i];
    uint32_t h0 = packhl(v.x, v.y), h1 = packhl(v.z, v.w);
    uint32_t l0 = packres(v.x, v.y, h0), l1 = packres(v.z, v.w, h1);
    ((uint32_t*)(hi + 4 * (size_t)i))[0] = h0; ((uint32_t*)(hi + 4 * (size_t)i))[1] = h1;
    ((uint32_t*)(lo + 4 * (size_t)i))[0] = l0; ((uint32_t*)(lo + 4 * (size_t)i))[1] = l1;
}

// ---------------- HMMA GEMM: C[m,n] = sum_k X[m,k]*W[n,k] ----------------
#define SRW  36
#define MATW (128*SRW)
#define BUFW (4*MATW)
#define GSM_BYTES (2*BUFW*4)

template<int MODE>
__global__ __launch_bounds__(256) void gemm_mma(const float* __restrict__ bias, float* __restrict__ Out)
{
    extern __shared__ char smch[];
    const uint32_t sb = smem_u32(smch);

    const int tid = threadIdx.x, lane = tid & 31, wid = tid >> 5;
    const int wm = wid & 3, wn = wid >> 2;
    const int g = lane >> 2, cc = lane & 3;
    const int n0 = blockIdx.x * 128, m0 = blockIdx.y * 128;

    const __nv_bfloat16 *Ahp, *Alp, *Whp, *Wlp;
    int z = 0;
    if (MODE == 1) {
        z = blockIdx.z;
        Ahp = g_xhi; Alp = g_xlo;
        Whp = g_whi + (size_t)z * D_ * D_; Wlp = g_wlo + (size_t)z * D_ * D_;
    } else {
        Ahp = g_ahi; Alp = g_alo;
        Whp = g_whi + (size_t)3 * D_ * D_; Wlp = g_wlo + (size_t)3 * D_ * D_;
    }

    const int r = tid >> 1, half = tid & 1;
    const size_t garow = (size_t)(m0 + r) * D_ + half * 32;
    const size_t gbrow = (size_t)(n0 + r) * D_ + half * 32;
    const uint32_t sdst = sb + (uint32_t)(r * SRW + half * 16) * 4;

    auto issue_chunk = [&](int c) {
        const int k0 = c * 64;
        const uint32_t d0 = sdst + (uint32_t)((c & 1) * BUFW) * 4;
        const __nv_bfloat16* pa = Ahp + garow + k0;
        const __nv_bfloat16* pl = Alp + garow + k0;
        const __nv_bfloat16* pb = Whp + gbrow + k0;
        const __nv_bfloat16* pq = Wlp + gbrow + k0;
        #pragma unroll
        for (int j = 0; j < 4; j++) {
            cpasync16(d0 + j * 16,                 pa + j * 8);
            cpasync16(d0 + MATW * 4 + j * 16,      pl + j * 8);
            cpasync16(d0 + 2 * MATW * 4 + j * 16,  pb + j * 8);
            cpasync16(d0 + 3 * MATW * 4 + j * 16,  pq + j * 8);
        }
    };

    float d[2][8][4] = {};

    issue_chunk(0);
    asm volatile("cp.async.commit_group;" ::: "memory");

    for (int c = 0; c < 16; c++) {
        if (c < 15) {
            issue_chunk(c + 1);
            asm volatile("cp.async.commit_group;" ::: "memory");
            asm volatile("cp.async.wait_group 1;" ::: "memory");
        } else {
            asm volatile("cp.async.wait_group 0;" ::: "memory");
        }
        __syncthreads();

        const uint32_t bufb = sb + (uint32_t)((c & 1) * BUFW) * 4;
        const uint32_t aA0 = ldmA_addr(bufb, SRW, wm * 32, lane);
        const uint32_t aA1 = ldmA_addr(bufb, SRW, wm * 32 + 16, lane);
        uint32_t bB[2][2];
        #pragma unroll
        for (int nq = 0; nq < 2; nq++)
            #pragma unroll
            for (int pr = 0; pr < 2; pr++)
                bB[nq][pr] = ldmB_addr(bufb + 2 * MATW * 4, SRW, wn * 64 + nq * 32 + pr * 16, lane);

        #pragma unroll
        for (int ks = 0; ks < 4; ks++) {
            uint32_t ah[2][4], al[2][4];
            ldm4(ah[0], aA0 + ks * 32);
            ldm4(ah[1], aA1 + ks * 32);
            ldm4(al[0], aA0 + MATW * 4 + ks * 32);
            ldm4(al[1], aA1 + MATW * 4 + ks * 32);
            #pragma unroll
            for (int nq = 0; nq < 2; nq++)
                #pragma unroll
                for (int pr = 0; pr < 2; pr++) {
                    uint32_t bhp[4], blp[4];
                    ldm4(bhp, bB[nq][pr] + ks * 32);
                    ldm4(blp, bB[nq][pr] + MATW * 4 + ks * 32);
                    #pragma unroll
                    for (int hf = 0; hf < 2; hf++)
                        #pragma unroll
                        for (int mi = 0; mi < 2; mi++) {
                            float* dd = d[mi][nq * 4 + pr * 2 + hf];
                            mma16816(dd, ah[mi], bhp + hf * 2);
                            mma16816(dd, ah[mi], blp + hf * 2);
                            mma16816(dd, al[mi], bhp + hf * 2);
                        }
                }
        }
        __syncthreads();
    }

    // epilogue
    #pragma unroll
    for (int mi = 0; mi < 2; mi++) {
        const int row = m0 + wm * 32 + mi * 16 + g;
        #pragma unroll
        for (int ni = 0; ni < 8; ni++) {
            const int col = n0 + wn * 64 + ni * 8 + cc * 2;
            float* dd = d[mi][ni];
            if (MODE == 1) {
                __nv_bfloat16* ohi = (z == 0) ? g_qhi : (z == 1) ? g_khi : g_vhi;
                __nv_bfloat16* olo = (z == 0) ? g_qlo : (z == 1) ? g_klo : g_vlo;
                int b = row >> 11, l = row & (L_ - 1);
                int hh = col >> 6, dp = col & 63;
                size_t base = ((size_t)(b * H_ + hh) * L_ + l) * HD_ + dp;
                uint32_t h0 = packhl(dd[0], dd[1]), h1 = packhl(dd[2], dd[3]);
                *(uint32_t*)(ohi + base)           = h0;
                *(uint32_t*)(ohi + base + 8 * HD_) = h1;
                *(uint32_t*)(olo + base)           = packres(dd[0], dd[1], h0);
                *(uint32_t*)(olo + base + 8 * HD_) = packres(dd[2], dd[3], h1);
            } else {
                float bx = bias[col], by = bias[col + 1];
                *(float2*)(Out + (size_t)row * D_ + col) =
                    make_float2(dd[0] + bx, dd[1] + by);
                *(float2*)(Out + (size_t)(row + 8) * D_ + col) =
                    make_float2(dd[2] + bx, dd[3] + by);
            }
        }
    }
}

// ---------------- tensor-core attention ----------------
#define SQ   36
#define SP   68
#define WQ_LO 2304            // words: Q lo offset
#define WK0   4608            // words: K double buffer (2 x 9216)
#define WV0   0               // words: phase-2 V double buffer (2 x 9216), overlays Q/K
#define WP_HI 18432           // words
#define WP_LO 22784           // words (WP_HI + 64*68)
#define ASM_BYTES (27136*4)   // 108544

__global__ __launch_bounds__(256) void attn_mma(float* __restrict__ A)
{
    extern __shared__ uint32_t s32[];
    __shared__ float ms[64], ls[64], pm[64][4], pl[64][4];

    const int tid = threadIdx.x, lane = tid & 31, wid = tid >> 5;
    const int g = lane >> 2, cc = lane & 3;
    const int wm = wid & 1,  wn = wid >> 1;    // phase 1: 2 m-warps x 4 n-warps
    const int wm2 = wid & 3, wn2 = wid >> 2;   // phase 2: 4 m-warps x 2 n-warps
    const int q0 = blockIdx.x * 64, h = blockIdx.y, b = blockIdx.z;
    const int bh = b * H_ + h;
    const __nv_bfloat16* qhi = g_qhi + (size_t)bh * L_ * HD_;
    const __nv_bfloat16* qlo = g_qlo + (size_t)bh * L_ * HD_;
    const __nv_bfloat16* khi = g_khi + (size_t)bh * L_ * HD_;
    const __nv_bfloat16* klo = g_klo + (size_t)bh * L_ * HD_;
    const __nv_bfloat16* vhi = g_vhi + (size_t)bh * L_ * HD_;
    const __nv_bfloat16* vlo = g_vlo + (size_t)bh * L_ * HD_;
    float* Ab = A + ((size_t)bh * L_ + q0) * L_;
    const uint32_t sb = smem_u32(s32);

    // Q tile 64x64 hi/lo -> smem
    {
        const int r = tid >> 2, qw = tid & 3;
        const __nv_bfloat16* sh = qhi + (size_t)(q0 + r) * HD_ + qw * 16;
        const __nv_bfloat16* sl = qlo + (size_t)(q0 + r) * HD_ + qw * 16;
        *(uint4*)&s32[r * SQ + qw * 8]             = *(const uint4*)sh;
        *(uint4*)&s32[r * SQ + qw * 8 + 4]         = *(const uint4*)(sh + 8);
        *(uint4*)&s32[WQ_LO + r * SQ + qw * 8]     = *(const uint4*)sl;
        *(uint4*)&s32[WQ_LO + r * SQ + qw * 8 + 4] = *(const uint4*)(sl + 8);
    }
    if (tid < 64) { ms[tid] = -1e30f; ls[tid] = 0.f; }

    auto loadK = [&](int kt) {
        const int r = tid >> 1, half = tid & 1;
        const uint32_t bo = WK0 + (kt & 1) * 9216;
        const __nv_bfloat16* sh = khi + (size_t)(kt * 128 + r) * HD_ + half * 32;
        const __nv_bfloat16* sl = klo + (size_t)(kt * 128 + r) * HD_ + half * 32;
        const uint32_t dh = sb + (bo + r * SQ + half * 16) * 4;
        const uint32_t dl = sb + (bo + 128 * SQ + r * SQ + half * 16) * 4;
        #pragma unroll
        for (int j = 0; j < 4; j++) {
            cpasync16(dh + j * 16, sh + j * 8);
            cpasync16(dl + j * 16, sl + j * 8);
        }
    };

    loadK(0);
    asm volatile("cp.async.commit_group;" ::: "memory");

    const uint32_t aQh0 = ldmA_addr(sb, SQ, wm * 32, lane);
    const uint32_t aQh1 = ldmA_addr(sb, SQ, wm * 32 + 16, lane);

    // ---------------- phase 1 ----------------
    for (int kt = 0; kt < 16; kt++) {
        if (kt < 15) {
            loadK(kt + 1);
            asm volatile("cp.async.commit_group;" ::: "memory");
            asm volatile("cp.async.wait_group 1;" ::: "memory");
        } else {
            asm volatile("cp.async.wait_group 0;" ::: "memory");
        }
        __syncthreads();

        const uint32_t Kb = sb + (WK0 + (kt & 1) * 9216) * 4;
        uint32_t bK[2];
        #pragma unroll
        for (int pr = 0; pr < 2; pr++)
            bK[pr] = ldmB_addr(Kb, SQ, wn * 32 + pr * 16, lane);

        float d[2][4][4] = {};
        #pragma unroll
        for (int ks = 0; ks < 4; ks++) {
            uint32_t ah[2][4], al[2][4];
            ldm4(ah[0], aQh0 + ks * 32);
            ldm4(ah[1], aQh1 + ks * 32);
            ldm4(al[0], aQh0 + WQ_LO * 4 + ks * 32);
            ldm4(al[1], aQh1 + WQ_LO * 4 + ks * 32);
            #pragma unroll
            for (int pr = 0; pr < 2; pr++) {
                uint32_t bhp[4], blp[4];
                ldm4(bhp, bK[pr] + ks * 32);
                ldm4(blp, bK[pr] + 128 * SQ * 4 + ks * 32);
                #pragma unroll
                for (int hf = 0; hf < 2; hf++)
                    #pragma unroll
                    for (int mi = 0; mi < 2; mi++) {
                        float* dd = d[mi][pr * 2 + hf];
                        mma16816(dd, ah[mi], bhp + hf * 2);
                        mma16816(dd, ah[mi], blp + hf * 2);
                        mma16816(dd, al[mi], bhp + hf * 2);
                    }
            }
        }
        // scale, write raw scores, per-row stats
        #pragma unroll
        for (int mi = 0; mi < 2; mi++)
        #pragma unroll
        for (int ch = 0; ch < 2; ch++) {
            const int row = wm * 32 + mi * 16 + g + 8 * ch;
            float v[8];
            #pragma unroll
            for (int nn = 0; nn < 4; nn++) {
                v[2*nn]   = d[mi][nn][2*ch]   * 0.125f;
                v[2*nn+1] = d[mi][nn][2*ch+1] * 0.125f;
                *(float2*)(Ab + (size_t)row * L_ + kt * 128 + wn * 32 + nn * 8 + cc * 2)
                    = make_float2(v[2*nn], v[2*nn+1]);
            }
            float mx = v[0];
            #pragma unroll
            for (int j = 1; j < 8; j++) mx = fmaxf(mx, v[j]);
            mx = fmaxf(mx, __shfl_xor_sync(0xffffffffu, mx, 1));
            mx = fmaxf(mx, __shfl_xor_sync(0xffffffffu, mx, 2));
            float e = 0.f;
            #pragma unroll
            for (int j = 0; j < 8; j++) e += __expf(v[j] - mx);
            e += __shfl_xor_sync(0xffffffffu, e, 1);
            e += __shfl_xor_sync(0xffffffffu, e, 2);
            if (cc == 0) { pm[row][wn] = mx; pl[row][wn] = e; }
        }
        __syncthreads();
        if (tid < 64) {
            float mo = ms[tid], lo = ls[tid];
            #pragma unroll
            for (int w = 0; w < 4; w++) {
                float mw = pm[tid][w], lw = pl[tid][w];
                float mn = fmaxf(mo, mw);
                lo = lo * __expf(mo - mn) + lw * __expf(mw - mn);
                mo = mn;
            }
            ms[tid] = mo; ls[tid] = lo;
        }
    }
    __syncthreads();
    if (tid < 64) ls[tid] = 1.0f / ls[tid];
    __syncthreads();

    // ---------------- phase 2 ----------------
    auto issueV = [&](int kt) {
        const int r = tid >> 1, half = tid & 1;
        const uint32_t bo = WV0 + (kt & 1) * 9216;
        const __nv_bfloat16* sh = vhi + (size_t)(kt * 128 + r) * HD_ + half * 32;
        const __nv_bfloat16* sl = vlo + (size_t)(kt * 128 + r) * HD_ + half * 32;
        const uint32_t dh = sb + (bo + r * SRW + half * 16) * 4;
        const uint32_t dl = sb + (bo + 4608 + r * SRW + half * 16) * 4;
        #pragma unroll
        for (int j = 0; j < 4; j++) {
            cpasync16(dh + j * 16, sh + j * 8);
            cpasync16(dl + j * 16, sl + j * 8);
        }
    };

    issueV(0);
    asm volatile("cp.async.commit_group;" ::: "memory");

    const uint32_t aP  = ldmA_addr(sb + WP_HI * 4, SP, wm2 * 16, lane);
    const uint32_t dPL = (WP_LO - WP_HI) * 4;

    float o[4][4] = {};
    for (int kt = 0; kt < 16; kt++) {
        if (kt < 15) {
            issueV(kt + 1);
            asm volatile("cp.async.commit_group;" ::: "memory");
        }
        // build P: readback own raw scores, finalize A, stage P hi/lo
        #pragma unroll
        for (int mi = 0; mi < 2; mi++)
        #pragma unroll
        for (int ch = 0; ch < 2; ch++) {
            const int row = wm * 32 + mi * 16 + g + 8 * ch;
            const float m = ms[row], il = ls[row];
            #pragma unroll
            for (int nn = 0; nn < 4; nn++) {
                float* ap = Ab + (size_t)row * L_ + kt * 128 + wn * 32 + nn * 8 + cc * 2;
                float2 s = *(float2*)ap;
                float p0 = __expf(s.x - m) * il;
                float p1 = __expf(s.y - m) * il;
                *(float2*)ap = make_float2(p0, p1);
                uint32_t hw = packhl(p0, p1);
                uint32_t lw = packres(p0, p1, hw);
                s32[WP_HI + row * SP + wn * 16 + nn * 4 + cc] = hw;
                s32[WP_LO + row * SP + wn * 16 + nn * 4 + cc] = lw;
            }
        }
        if (kt < 15) asm volatile("cp.async.wait_group 1;" ::: "memory");
        else         asm volatile("cp.async.wait_group 0;" ::: "memory");
        __syncthreads();   // V(kt) visible + P staged

        const uint32_t Vb = sb + (WV0 + (kt & 1) * 9216) * 4;
        uint32_t bV[2];
        #pragma unroll
        for (int np = 0; np < 2; np++)
            bV[np] = ldmBT_addr(Vb, SRW, wn2 * 32 + np * 16, lane);

        #pragma unroll
        for (int ks = 0; ks < 8; ks++) {
            uint32_t ah2[4], al2[4];
            ldm4(ah2, aP + ks * 32);
            ldm4(al2, aP + dPL + ks * 32);
            #pragma unroll
            for (int np = 0; np < 2; np++) {
                uint32_t bhp[4], blp[4];
                ldm4t(bhp, bV[np] + ks * 16 * SRW * 4);
                ldm4t(blp, bV[np] + 4608 * 4 + ks * 16 * SRW * 4);
                #pragma unroll
                for (int hf = 0; hf < 2; hf++) {
                    float* oo = o[np * 2 + hf];
                    mma16816(oo, ah2, bhp + hf * 2);
                    mma16816(oo, al2, bhp + hf * 2);
                    mma16816(oo, ah2, blp + hf * 2);
                }
            }
        }
        __syncthreads();   // protect V buffer + P region before next chunk
    }

    // epilogue: O -> g_ahi/g_alo at [b*L + q0+row][h*64 + col]
    #pragma unroll
    for (int nn = 0; nn < 4; nn++)
    #pragma unroll
    for (int ch = 0; ch < 2; ch++) {
        const int row = wm2 * 16 + g + 8 * ch;
        const int col = wn2 * 32 + nn * 8 + cc * 2;
        const size_t base = ((size_t)(b * L_ + q0 + row)) * D_ + h * HD_ + col;
        float v0 = o[nn][2 * ch], v1 = o[nn][2 * ch + 1];
        uint32_t hw = packhl(v0, v1);
        *(uint32_t*)(g_ahi + base) = hw;
        *(uint32_t*)(g_alo + base) = packres(v0, v1, hw);
    }
}

extern "C" void kernel_launch(void* const* d_in, const int* in_sizes, int n_in,
                              void* d_out, int out_size) {
    const float* x  = (const float*)d_in[0];
    // d_in[1] = key_indices: unused by the reference computation
    const float* bo = (const float*)d_in[6];
    float* out = (float*)d_out;
    float* A   = out + (size_t)M_ * D_;

    cudaFuncSetAttribute(gemm_mma<1>, cudaFuncAttributeMaxDynamicSharedMemorySize, GSM_BYTES);
    cudaFuncSetAttribute(gemm_mma<0>, cudaFuncAttributeMaxDynamicSharedMemorySize, GSM_BYTES);
    cudaFuncSetAttribute(attn_mma,    cudaFuncAttributeMaxDynamicSharedMemorySize, ASM_BYTES);

    // bf16 hi/lo splits of x and the 4 weights
    split_kernel<<<(M_*D_/4 + 255)/256, 256>>>(x, 0, 0, M_*D_/4);
    for (int z = 0; z < 4; z++)
        split_kernel<<<(D_*D_/4 + 255)/256, 256>>>((const float*)d_in[2 + z], 1, z, D_*D_/4);

    // q,k,v projections on tensor cores -> bf16 hi/lo q/k/v
    gemm_mma<1><<<dim3(8, 64, 3), 256, GSM_BYTES>>>(nullptr, nullptr);

    // tensor-core attention: A materialized + attn output as hi/lo
    attn_mma<<<dim3(32, 16, 4), 256, ASM_BYTES>>>(A);

    // output projection + bias on tensor cores
    gemm_mma<0><<<dim3(8, 64, 1), 256, GSM_BYTES>>>(bo, out);
}